// round 2
// baseline (speedup 1.0000x reference)
#include <cuda_runtime.h>
#include <math.h>

#define HW        4096          // H*W
#define CC        3             // channels
#define FF        64            // freq bins
#define BB        32            // batch
#define NSLAB     (BB*CC*FF)    // 6144 (b,c,f) slabs
#define NUM_KEEP  32
#define BN_EPS    1e-5f

// Scratch (no device allocation allowed -> __device__ globals)
__device__ float g_pooled[NSLAB];
__device__ float g_mask[NSLAB];

// Streaming (evict-first) 16B store: don't let output lines evict x_freq in L2.
__device__ __forceinline__ void stcs4(float4* p, float4 v) {
    asm volatile("st.global.cs.v4.f32 [%0], {%1,%2,%3,%4};"
                 :: "l"(p), "f"(v.x), "f"(v.y), "f"(v.z), "f"(v.w)
                 : "memory");
}

// ---------------------------------------------------------------------------
// Kernel A: mean over H*W per (b,c,f) slab + zero-fill of the second output
// (x_pruned_2k), which is independent of all the scoring math. One block per
// slab; 256 threads x 4 float4 = 4096 floats read, 4096 floats of zeros
// written (streaming stores). Read+write streams overlap in DRAM.
// ---------------------------------------------------------------------------
__global__ void pool_kernel(const float* __restrict__ x,
                            float* __restrict__ out2) {
    const int slab = blockIdx.x;
    const int t = threadIdx.x;
    const float4* __restrict__ p =
        reinterpret_cast<const float4*>(x) + (size_t)slab * (HW / 4);
    float4* __restrict__ o2 =
        reinterpret_cast<float4*>(out2) + (size_t)slab * (HW / 4);

    const float4 z = make_float4(0.f, 0.f, 0.f, 0.f);

    float s = 0.f;
#pragma unroll
    for (int i = 0; i < 4; i++) {
        float4 v = p[t + i * 256];
        s += (v.x + v.y) + (v.z + v.w);
        stcs4(o2 + t + i * 256, z);
    }
#pragma unroll
    for (int o = 16; o > 0; o >>= 1)
        s += __shfl_xor_sync(0xffffffffu, s, o);

    __shared__ float ws[8];
    if ((t & 31) == 0) ws[t >> 5] = s;
    __syncthreads();
    if (t == 0) {
        float tot = 0.f;
#pragma unroll
        for (int i = 0; i < 8; i++) tot += ws[i];
        g_pooled[slab] = tot * (1.0f / HW);
    }
}

// ---------------------------------------------------------------------------
// Kernel B: all the tiny scoring math + top-32 mask. One block per batch b,
// 64 threads (thread = freq index g).
// ---------------------------------------------------------------------------
__device__ __forceinline__ float sigmoidf(float v) {
    return 1.0f / (1.0f + expf(-v));
}

__global__ void score_kernel(const float* __restrict__ conv_w,
                             const float* __restrict__ conv_b,
                             const float* __restrict__ fc_w,
                             const float* __restrict__ fc_b,
                             const float* __restrict__ conv1_w,
                             const float* __restrict__ conv1_b,
                             const float* __restrict__ convr_w,
                             const float* __restrict__ convr_b,
                             const float* __restrict__ convl_w,
                             const float* __restrict__ convl_b,
                             const float* __restrict__ bn_gamma,
                             const float* __restrict__ bn_beta,
                             const float* __restrict__ bn_mean,
                             const float* __restrict__ bn_var,
                             const float* __restrict__ a_ptr) {
    const int b = blockIdx.x;
    const int g = threadIdx.x;   // 0..63

    __shared__ float pooled[CC][FF];
    __shared__ float xconv[CC][FF];
    __shared__ float scores[CC][FF];
    __shared__ float fin[CC][FF];
    __shared__ float xrc[CC][2][8];
    __shared__ float xrc2[CC][2][8];
    __shared__ float ar[CC][8];
    __shared__ float al[CC][8];

#pragma unroll
    for (int c = 0; c < CC; c++)
        pooled[c][g] = g_pooled[(b * CC + c) * FF + g];
    __syncthreads();

    // x_conv = pooled @ conv_w^T + conv_b   (w[g,f] = conv_w[g*FF+f])
#pragma unroll
    for (int c = 0; c < CC; c++) {
        float s = conv_b[g];
        for (int f = 0; f < FF; f++)
            s = fmaf(pooled[c][f], conv_w[g * FF + f], s);
        xconv[c][g] = s;
    }
    __syncthreads();

    // scores = sigmoid(x_conv @ fc_w^T + fc_b)
#pragma unroll
    for (int c = 0; c < CC; c++) {
        float s = fc_b[g];
        for (int f = 0; f < FF; f++)
            s = fmaf(xconv[c][f], fc_w[g * FF + f], s);
        scores[c][g] = sigmoidf(s);
    }

    // row / col means of pooled viewed as 8x8
    if (g < CC * 8) {
        int c = g / 8, i = g % 8;
        float r = 0.f, co = 0.f;
#pragma unroll
        for (int j = 0; j < 8; j++) {
            r  += pooled[c][i * 8 + j];
            co += pooled[c][j * 8 + i];
        }
        xrc[c][0][i] = r * 0.125f;
        xrc[c][1][i] = co * 0.125f;
    }
    __syncthreads();

    // conv1 (mixes channels) + BN + sigmoid
    if (g < CC * 8) {
        int d = g / 8, i = g % 8;
        float inv = rsqrtf(bn_var[d] + BN_EPS);
#pragma unroll
        for (int s2 = 0; s2 < 2; s2++) {
            float v = conv1_b[d];
#pragma unroll
            for (int c = 0; c < CC; c++)
                v = fmaf(xrc[c][s2][i], conv1_w[d * CC + c], v);
            v = (v - bn_mean[d]) * inv;
            v = v * bn_gamma[d] + bn_beta[d];
            xrc2[d][s2][i] = sigmoidf(v);
        }
    }
    __syncthreads();

    // a_r, a_l (channel-mixing 1x1 convs + sigmoid)
    if (g < CC * 8) {
        int d = g / 8, i = g % 8;
        float vr = convr_b[d], vl = convl_b[d];
#pragma unroll
        for (int c = 0; c < CC; c++) {
            vr = fmaf(xrc2[c][0][i], convr_w[d * CC + c], vr);
            vl = fmaf(xrc2[c][1][i], convl_w[d * CC + c], vl);
        }
        ar[d][i] = sigmoidf(vr);
        al[d][i] = sigmoidf(vl);
    }
    __syncthreads();

    // final = a * (a_r outer a_l) + (1-a) * scores
    const float a = *a_ptr;
    const int i = g >> 3, j = g & 7;
#pragma unroll
    for (int c = 0; c < CC; c++)
        fin[c][g] = a * ar[c][i] * al[c][j] + (1.0f - a) * scores[c][g];
    __syncthreads();

    // top-32 via stable rank (ties -> lower index wins, matches jax top_k)
#pragma unroll
    for (int c = 0; c < CC; c++) {
        float v = fin[c][g];
        int rank = 0;
        for (int f = 0; f < FF; f++) {
            float u = fin[c][f];
            rank += (u > v) || (u == v && f < g);
        }
        g_mask[(b * CC + c) * FF + g] = (rank < NUM_KEEP) ? 1.0f : 0.0f;
    }
}

// ---------------------------------------------------------------------------
// Kernel C: first output only. Kept slabs: copy (reads should hit L2 —
// x_freq was just streamed through and output writes are evict-first).
// Dropped slabs: write zeros, no read. 256 threads x 4 float4 per slab.
// ---------------------------------------------------------------------------
__global__ void prune_kernel(const float* __restrict__ x,
                             float* __restrict__ out) {
    const int slab = blockIdx.x;
    const int t = threadIdx.x;
    float4* __restrict__ o =
        reinterpret_cast<float4*>(out) + (size_t)slab * (HW / 4);

    const bool keep = (g_mask[slab] != 0.0f);

    if (keep) {
        const float4* __restrict__ p =
            reinterpret_cast<const float4*>(x) + (size_t)slab * (HW / 4);
#pragma unroll
        for (int i = 0; i < 4; i++)
            stcs4(o + t + i * 256, p[t + i * 256]);
    } else {
        const float4 z = make_float4(0.f, 0.f, 0.f, 0.f);
#pragma unroll
        for (int i = 0; i < 4; i++)
            stcs4(o + t + i * 256, z);
    }
}

// ---------------------------------------------------------------------------
extern "C" void kernel_launch(void* const* d_in, const int* in_sizes, int n_in,
                              void* d_out, int out_size) {
    const float* x_freq  = (const float*)d_in[0];
    const float* conv_w  = (const float*)d_in[1];
    const float* conv_b  = (const float*)d_in[2];
    const float* fc_w    = (const float*)d_in[3];
    const float* fc_b    = (const float*)d_in[4];
    const float* conv1_w = (const float*)d_in[5];
    const float* conv1_b = (const float*)d_in[6];
    const float* convr_w = (const float*)d_in[7];
    const float* convr_b = (const float*)d_in[8];
    const float* convl_w = (const float*)d_in[9];
    const float* convl_b = (const float*)d_in[10];
    const float* bn_gamma = (const float*)d_in[11];
    const float* bn_beta  = (const float*)d_in[12];
    const float* bn_mean  = (const float*)d_in[13];
    const float* bn_var   = (const float*)d_in[14];
    const float* a_scalar = (const float*)d_in[15];

    float* out  = (float*)d_out;                       // x_pruned
    float* out2 = (float*)d_out + (size_t)NSLAB * HW;  // x_pruned_2k (zeros)

    pool_kernel<<<NSLAB, 256>>>(x_freq, out2);
    score_kernel<<<BB, FF>>>(conv_w, conv_b, fc_w, fc_b,
                             conv1_w, conv1_b, convr_w, convr_b,
                             convl_w, convl_b,
                             bn_gamma, bn_beta, bn_mean, bn_var, a_scalar);
    prune_kernel<<<NSLAB, 256>>>(x_freq, out);
}

// round 3
// speedup vs baseline: 1.0497x; 1.0497x over previous
#include <cuda_runtime.h>
#include <math.h>

#define HW        4096          // H*W
#define CC        3             // channels
#define FF        64            // freq bins
#define BB        32            // batch
#define NSLAB     (BB*CC*FF)    // 6144 (b,c,f) slabs
#define NUM_KEEP  32
#define BN_EPS    1e-5f

// Scratch (no device allocation allowed -> __device__ globals)
__device__ float g_pooled[NSLAB];
__device__ float g_mask[NSLAB];

// Streaming (evict-first) 16B store: output is never re-read -> keep it from
// evicting x_freq in L2.
__device__ __forceinline__ void stcs4(float4* p, float4 v) {
    asm volatile("st.global.cs.v4.f32 [%0], {%1,%2,%3,%4};"
                 :: "l"(p), "f"(v.x), "f"(v.y), "f"(v.z), "f"(v.w)
                 : "memory");
}

// ---------------------------------------------------------------------------
// Kernel A: mean over H*W per (b,c,f) slab. READ ONLY — x_freq must stay
// L2-resident for the prune pass. One block per 2 slabs (32KB): each thread
// front-batches 8 float4 loads (MLP_p1=8) to hide DRAM latency.
// ---------------------------------------------------------------------------
__global__ void pool_kernel(const float* __restrict__ x) {
    const int blk = blockIdx.x;          // handles slabs 2*blk, 2*blk+1
    const int t = threadIdx.x;           // 0..255
    const float4* __restrict__ p =
        reinterpret_cast<const float4*>(x) + (size_t)blk * (2 * HW / 4);

    float4 v[8];
#pragma unroll
    for (int i = 0; i < 8; i++)
        v[i] = p[t + i * 256];           // i<4 -> slab0, i>=4 -> slab1

    float s0 = 0.f, s1 = 0.f;
#pragma unroll
    for (int i = 0; i < 4; i++)
        s0 += (v[i].x + v[i].y) + (v[i].z + v[i].w);
#pragma unroll
    for (int i = 4; i < 8; i++)
        s1 += (v[i].x + v[i].y) + (v[i].z + v[i].w);

#pragma unroll
    for (int o = 16; o > 0; o >>= 1) {
        s0 += __shfl_xor_sync(0xffffffffu, s0, o);
        s1 += __shfl_xor_sync(0xffffffffu, s1, o);
    }

    __shared__ float ws0[8], ws1[8];
    if ((t & 31) == 0) { ws0[t >> 5] = s0; ws1[t >> 5] = s1; }
    __syncthreads();
    if (t == 0) {
        float a = 0.f, b = 0.f;
#pragma unroll
        for (int i = 0; i < 8; i++) { a += ws0[i]; b += ws1[i]; }
        g_pooled[2 * blk]     = a * (1.0f / HW);
        g_pooled[2 * blk + 1] = b * (1.0f / HW);
    }
}

// ---------------------------------------------------------------------------
// Kernel B: all the tiny scoring math + top-32 mask. One block per batch b,
// 64 threads (thread = freq index g).
// ---------------------------------------------------------------------------
__device__ __forceinline__ float sigmoidf(float v) {
    return 1.0f / (1.0f + expf(-v));
}

__global__ void score_kernel(const float* __restrict__ conv_w,
                             const float* __restrict__ conv_b,
                             const float* __restrict__ fc_w,
                             const float* __restrict__ fc_b,
                             const float* __restrict__ conv1_w,
                             const float* __restrict__ conv1_b,
                             const float* __restrict__ convr_w,
                             const float* __restrict__ convr_b,
                             const float* __restrict__ convl_w,
                             const float* __restrict__ convl_b,
                             const float* __restrict__ bn_gamma,
                             const float* __restrict__ bn_beta,
                             const float* __restrict__ bn_mean,
                             const float* __restrict__ bn_var,
                             const float* __restrict__ a_ptr) {
    const int b = blockIdx.x;
    const int g = threadIdx.x;   // 0..63

    __shared__ float pooled[CC][FF];
    __shared__ float xconv[CC][FF];
    __shared__ float scores[CC][FF];
    __shared__ float fin[CC][FF];
    __shared__ float xrc[CC][2][8];
    __shared__ float xrc2[CC][2][8];
    __shared__ float ar[CC][8];
    __shared__ float al[CC][8];

#pragma unroll
    for (int c = 0; c < CC; c++)
        pooled[c][g] = g_pooled[(b * CC + c) * FF + g];
    __syncthreads();

    // x_conv = pooled @ conv_w^T + conv_b
#pragma unroll
    for (int c = 0; c < CC; c++) {
        float s = conv_b[g];
        for (int f = 0; f < FF; f++)
            s = fmaf(pooled[c][f], conv_w[g * FF + f], s);
        xconv[c][g] = s;
    }
    __syncthreads();

    // scores = sigmoid(x_conv @ fc_w^T + fc_b)
#pragma unroll
    for (int c = 0; c < CC; c++) {
        float s = fc_b[g];
        for (int f = 0; f < FF; f++)
            s = fmaf(xconv[c][f], fc_w[g * FF + f], s);
        scores[c][g] = sigmoidf(s);
    }

    // row / col means of pooled viewed as 8x8
    if (g < CC * 8) {
        int c = g / 8, i = g % 8;
        float r = 0.f, co = 0.f;
#pragma unroll
        for (int j = 0; j < 8; j++) {
            r  += pooled[c][i * 8 + j];
            co += pooled[c][j * 8 + i];
        }
        xrc[c][0][i] = r * 0.125f;
        xrc[c][1][i] = co * 0.125f;
    }
    __syncthreads();

    // conv1 (mixes channels) + BN + sigmoid
    if (g < CC * 8) {
        int d = g / 8, i = g % 8;
        float inv = rsqrtf(bn_var[d] + BN_EPS);
#pragma unroll
        for (int s2 = 0; s2 < 2; s2++) {
            float v = conv1_b[d];
#pragma unroll
            for (int c = 0; c < CC; c++)
                v = fmaf(xrc[c][s2][i], conv1_w[d * CC + c], v);
            v = (v - bn_mean[d]) * inv;
            v = v * bn_gamma[d] + bn_beta[d];
            xrc2[d][s2][i] = sigmoidf(v);
        }
    }
    __syncthreads();

    // a_r, a_l (channel-mixing 1x1 convs + sigmoid)
    if (g < CC * 8) {
        int d = g / 8, i = g % 8;
        float vr = convr_b[d], vl = convl_b[d];
#pragma unroll
        for (int c = 0; c < CC; c++) {
            vr = fmaf(xrc2[c][0][i], convr_w[d * CC + c], vr);
            vl = fmaf(xrc2[c][1][i], convl_w[d * CC + c], vl);
        }
        ar[d][i] = sigmoidf(vr);
        al[d][i] = sigmoidf(vl);
    }
    __syncthreads();

    // final = a * (a_r outer a_l) + (1-a) * scores
    const float a = *a_ptr;
    const int i = g >> 3, j = g & 7;
#pragma unroll
    for (int c = 0; c < CC; c++)
        fin[c][g] = a * ar[c][i] * al[c][j] + (1.0f - a) * scores[c][g];
    __syncthreads();

    // top-32 via stable rank (ties -> lower index wins, matches jax top_k)
#pragma unroll
    for (int c = 0; c < CC; c++) {
        float v = fin[c][g];
        int rank = 0;
        for (int f = 0; f < FF; f++) {
            float u = fin[c][f];
            rank += (u > v) || (u == v && f < g);
        }
        g_mask[(b * CC + c) * FF + g] = (rank < NUM_KEEP) ? 1.0f : 0.0f;
    }
}

// ---------------------------------------------------------------------------
// Kernel C: writes BOTH outputs with streaming (.cs) stores so the output
// never evicts x_freq from L2. slab < NSLAB: x_pruned (copy if kept -- read
// should hit L2 since pool just streamed x -- zeros if dropped, no read).
// slab >= NSLAB: x_pruned_2k zero-fill. 256 threads x 4 float4 per slab.
// ---------------------------------------------------------------------------
__global__ void prune_kernel(const float* __restrict__ x,
                             float* __restrict__ out) {
    const int slab = blockIdx.x;
    const int t = threadIdx.x;
    float4* __restrict__ o =
        reinterpret_cast<float4*>(out) + (size_t)slab * (HW / 4);

    bool keep = false;
    if (slab < NSLAB) keep = (g_mask[slab] != 0.0f);

    if (keep) {
        const float4* __restrict__ p =
            reinterpret_cast<const float4*>(x) + (size_t)slab * (HW / 4);
        float4 v[4];
#pragma unroll
        for (int i = 0; i < 4; i++)
            v[i] = p[t + i * 256];
#pragma unroll
        for (int i = 0; i < 4; i++)
            stcs4(o + t + i * 256, v[i]);
    } else {
        const float4 z = make_float4(0.f, 0.f, 0.f, 0.f);
#pragma unroll
        for (int i = 0; i < 4; i++)
            stcs4(o + t + i * 256, z);
    }
}

// ---------------------------------------------------------------------------
extern "C" void kernel_launch(void* const* d_in, const int* in_sizes, int n_in,
                              void* d_out, int out_size) {
    const float* x_freq  = (const float*)d_in[0];
    const float* conv_w  = (const float*)d_in[1];
    const float* conv_b  = (const float*)d_in[2];
    const float* fc_w    = (const float*)d_in[3];
    const float* fc_b    = (const float*)d_in[4];
    const float* conv1_w = (const float*)d_in[5];
    const float* conv1_b = (const float*)d_in[6];
    const float* convr_w = (const float*)d_in[7];
    const float* convr_b = (const float*)d_in[8];
    const float* convl_w = (const float*)d_in[9];
    const float* convl_b = (const float*)d_in[10];
    const float* bn_gamma = (const float*)d_in[11];
    const float* bn_beta  = (const float*)d_in[12];
    const float* bn_mean  = (const float*)d_in[13];
    const float* bn_var   = (const float*)d_in[14];
    const float* a_scalar = (const float*)d_in[15];

    float* out = (float*)d_out;

    pool_kernel<<<NSLAB / 2, 256>>>(x_freq);
    score_kernel<<<BB, FF>>>(conv_w, conv_b, fc_w, fc_b,
                             conv1_w, conv1_b, convr_w, convr_b,
                             convl_w, convl_b,
                             bn_gamma, bn_beta, bn_mean, bn_var, a_scalar);
    prune_kernel<<<2 * NSLAB, 256>>>(x_freq, out);
}